// round 8
// baseline (speedup 1.0000x reference)
#include <cuda_runtime.h>
#include <math.h>

#define BB 8192
#define TT 128
#define HH 128
#define NSTEPS 30
#define KC 16

// ---------------- scratch (device globals; no allocation allowed) ----------------
__device__ float g_xsT[(size_t)TT * BB * HH];   // conv output, layout [t][b][h]
__device__ float g_h [2][(size_t)BB * HH];      // encoder hidden ping-pong
__device__ float g_hd[2][(size_t)BB * HH];      // decoder hidden ping-pong
__device__ float g_m1[(size_t)BB * 256];        // mlp fc1 out
__device__ float g_m2[(size_t)BB * 64];         // mlp fc2 out
__device__ float g_present[(size_t)BB * 6];     // running present accumulator

__device__ __forceinline__ float sigmoidf_(float x) { return 1.0f / (1.0f + expf(-x)); }

// ---------------- conv1d(k=3,pad=1) + relu + batchnorm -> g_xsT[t][b][h] ----------------
__global__ void conv_bn_kernel(const float* __restrict__ past,
                               const float* __restrict__ cw,
                               const float* __restrict__ cb,
                               const float* __restrict__ bn_g,
                               const float* __restrict__ bn_b,
                               const float* __restrict__ bn_m,
                               const float* __restrict__ bn_v)
{
    int bt = blockIdx.x;
    int b = bt >> 7;          // / 128
    int t = bt & 127;
    int h = threadIdx.x;

    float scale = bn_g[0] * rsqrtf(bn_v[0] + 1e-5f);
    float shift = bn_b[0] - bn_m[0] * scale;

    float pv[6][3];
#pragma unroll
    for (int c = 0; c < 6; ++c)
#pragma unroll
        for (int k = 0; k < 3; ++k) {
            int tt = t + k - 1;
            pv[c][k] = (tt >= 0 && tt < TT) ? past[(size_t)b * 768 + c * 128 + tt] : 0.0f;
        }

    float acc = cb[h];
#pragma unroll
    for (int c = 0; c < 6; ++c)
#pragma unroll
        for (int k = 0; k < 3; ++k)
            acc = fmaf(pv[c][k], cw[h * 18 + c * 3 + k], acc);

    acc = fmaxf(acc, 0.0f);
    acc = acc * scale + shift;
    g_xsT[((size_t)t * BB + b) * HH + h] = acc;
}

// ---------------- present0 = past[:, :, T-1] ----------------
__global__ void present_init_kernel(const float* __restrict__ past)
{
    int i = blockIdx.x * blockDim.x + threadIdx.x;
    if (i >= BB * 6) return;
    int b = i / 6, c = i % 6;
    g_present[i] = past[(size_t)b * 768 + c * 128 + (TT - 1)];
}

// ---------------- fused GRU step: gates GEMM (K = [x|h] concat) + pointwise update --------
// Tile: 64 rows (batch) x 64 cols (hidden) per CTA, 256 threads, 4x4 per thread,
// 4 accumulator sets (r, z, in, hn); only 3 active per K-phase.
__global__ __launch_bounds__(256, 2) void gru_step_kernel(
    const float* __restrict__ Ax,   // [B][128] x-input (may be null when hasx == 0)
    const float* __restrict__ Ah,   // [B][128] h_in
    const float* __restrict__ Wih,  // [384][128]
    const float* __restrict__ Whh,  // [384][128]
    const float* __restrict__ bih,
    const float* __restrict__ bhh,
    float* __restrict__ Hout,       // [B][128]
    int hasx)
{
    __shared__ float As[KC][68];    // [k][row], padded
    __shared__ float Ws[KC][196];   // [k][gate*64 + jj], padded

    const int tid = threadIdx.x;
    const int tx = tid & 15;        // col group
    const int ty = tid >> 4;        // row group
    const int bm = blockIdx.x * 64;
    const int bj = blockIdx.y * 64;

    float aR[16], aZ[16], aIN[16], aHN[16];
#pragma unroll
    for (int i = 0; i < 16; ++i) { aR[i] = 0.f; aZ[i] = 0.f; aIN[i] = 0.f; aHN[i] = 0.f; }

    const int lrow = tid >> 2;          // 0..63
    const int lk0  = (tid & 3) * 4;     // 0,4,8,12

#pragma unroll
    for (int phase = 0; phase < 2; ++phase) {
        if (phase == 0 && !hasx) continue;
        const float* __restrict__ A = phase ? Ah : Ax;
        const float* __restrict__ W = phase ? Whh : Wih;

        for (int kc = 0; kc < 128; kc += KC) {
            __syncthreads();
            {
                float4 v = *reinterpret_cast<const float4*>(&A[(size_t)(bm + lrow) * HH + kc + lk0]);
                As[lk0 + 0][lrow] = v.x; As[lk0 + 1][lrow] = v.y;
                As[lk0 + 2][lrow] = v.z; As[lk0 + 3][lrow] = v.w;
            }
#pragma unroll
            for (int it = 0; it < 3; ++it) {
                int r  = lrow + it * 64;        // 0..191
                int gg = r >> 6, jj = r & 63;
                float4 v = *reinterpret_cast<const float4*>(
                    &W[(size_t)(gg * 128 + bj + jj) * HH + kc + lk0]);
                Ws[lk0 + 0][r] = v.x; Ws[lk0 + 1][r] = v.y;
                Ws[lk0 + 2][r] = v.z; Ws[lk0 + 3][r] = v.w;
            }
            __syncthreads();

#pragma unroll
            for (int k = 0; k < KC; ++k) {
                float4 a4 = *reinterpret_cast<const float4*>(&As[k][ty * 4]);
                float4 w0 = *reinterpret_cast<const float4*>(&Ws[k][tx * 4]);
                float4 w1 = *reinterpret_cast<const float4*>(&Ws[k][64 + tx * 4]);
                float4 w2 = *reinterpret_cast<const float4*>(&Ws[k][128 + tx * 4]);
                float a[4]  = {a4.x, a4.y, a4.z, a4.w};
                float wr[4] = {w0.x, w0.y, w0.z, w0.w};
                float wz[4] = {w1.x, w1.y, w1.z, w1.w};
                float wn[4] = {w2.x, w2.y, w2.z, w2.w};
#pragma unroll
                for (int i = 0; i < 4; ++i)
#pragma unroll
                    for (int j = 0; j < 4; ++j) {
                        aR[i * 4 + j] = fmaf(a[i], wr[j], aR[i * 4 + j]);
                        aZ[i * 4 + j] = fmaf(a[i], wz[j], aZ[i * 4 + j]);
                        if (phase == 0) aIN[i * 4 + j] = fmaf(a[i], wn[j], aIN[i * 4 + j]);
                        else            aHN[i * 4 + j] = fmaf(a[i], wn[j], aHN[i * 4 + j]);
                    }
            }
        }
    }

    // ---- fused GRU pointwise epilogue ----
#pragma unroll
    for (int j = 0; j < 4; ++j) {
        int col = bj + tx * 4 + j;
        float br  = bih[col] + bhh[col];
        float bz  = bih[128 + col] + bhh[128 + col];
        float bin = bih[256 + col];
        float bhn = bhh[256 + col];
#pragma unroll
        for (int i = 0; i < 4; ++i) {
            int row = bm + ty * 4 + i;
            float r = sigmoidf_(aR[i * 4 + j] + br);
            float z = sigmoidf_(aZ[i * 4 + j] + bz);
            float n = tanhf(aIN[i * 4 + j] + bin + r * (aHN[i * 4 + j] + bhn));
            float hp = Ah[(size_t)row * HH + col];
            Hout[(size_t)row * HH + col] = (1.0f - z) * n + z * hp;
        }
    }
}

// ---------------- generic tiled GEMM: C[M][N] = act(A[M][K] @ W[N][K]^T + bias) ----------
template <bool RELU>
__global__ __launch_bounds__(256) void gemm_bias_act_kernel(
    const float* __restrict__ A, const float* __restrict__ W,
    const float* __restrict__ bias, float* __restrict__ C,
    int K, int N)
{
    __shared__ float As[KC][68];
    __shared__ float Ws[KC][68];

    const int tid = threadIdx.x;
    const int tx = tid & 15, ty = tid >> 4;
    const int bm = blockIdx.x * 64;
    const int bn = blockIdx.y * 64;

    float acc[16];
#pragma unroll
    for (int i = 0; i < 16; ++i) acc[i] = 0.f;

    const int lrow = tid >> 2;
    const int lk0  = (tid & 3) * 4;

    for (int kc = 0; kc < K; kc += KC) {
        __syncthreads();
        {
            float4 v = *reinterpret_cast<const float4*>(&A[(size_t)(bm + lrow) * K + kc + lk0]);
            As[lk0 + 0][lrow] = v.x; As[lk0 + 1][lrow] = v.y;
            As[lk0 + 2][lrow] = v.z; As[lk0 + 3][lrow] = v.w;
        }
        {
            float4 v = *reinterpret_cast<const float4*>(&W[(size_t)(bn + lrow) * K + kc + lk0]);
            Ws[lk0 + 0][lrow] = v.x; Ws[lk0 + 1][lrow] = v.y;
            Ws[lk0 + 2][lrow] = v.z; Ws[lk0 + 3][lrow] = v.w;
        }
        __syncthreads();
#pragma unroll
        for (int k = 0; k < KC; ++k) {
            float4 a4 = *reinterpret_cast<const float4*>(&As[k][ty * 4]);
            float4 w4 = *reinterpret_cast<const float4*>(&Ws[k][tx * 4]);
            float a[4] = {a4.x, a4.y, a4.z, a4.w};
            float w[4] = {w4.x, w4.y, w4.z, w4.w};
#pragma unroll
            for (int i = 0; i < 4; ++i)
#pragma unroll
                for (int j = 0; j < 4; ++j)
                    acc[i * 4 + j] = fmaf(a[i], w[j], acc[i * 4 + j]);
        }
    }

#pragma unroll
    for (int j = 0; j < 4; ++j) {
        int col = bn + tx * 4 + j;
        float b = bias[col];
#pragma unroll
        for (int i = 0; i < 4; ++i) {
            float v = acc[i * 4 + j] + b;
            if (RELU) v = fmaxf(v, 0.0f);
            C[(size_t)(bm + ty * 4 + i) * N + col] = v;
        }
    }
}

// ---------------- fc3 + present accumulate + output write ----------------
__global__ void mlp3_kernel(const float* __restrict__ W,   // [6][64]
                            const float* __restrict__ bias,
                            float* __restrict__ out, int s)
{
    int i = blockIdx.x * blockDim.x + threadIdx.x;
    if (i >= BB * 6) return;
    int b = i / 6, c = i % 6;
    float acc = bias[c];
    const float* arow = &g_m2[(size_t)b * 64];
    const float* wrow = &W[c * 64];
#pragma unroll
    for (int k = 0; k < 64; ++k) acc = fmaf(arow[k], wrow[k], acc);
    float p = g_present[i] + acc;
    g_present[i] = p;
    out[(size_t)b * (6 * NSTEPS) + c * NSTEPS + s] = p;
}

// ---------------- launcher ----------------
extern "C" void kernel_launch(void* const* d_in, const int* in_sizes, int n_in,
                              void* d_out, int out_size)
{
    const float* past    = (const float*)d_in[0];
    const float* conv_w  = (const float*)d_in[1];
    const float* conv_b  = (const float*)d_in[2];
    const float* bn_g    = (const float*)d_in[3];
    const float* bn_b    = (const float*)d_in[4];
    const float* bn_m    = (const float*)d_in[5];
    const float* bn_v    = (const float*)d_in[6];
    const float* enc_wih = (const float*)d_in[7];
    const float* enc_whh = (const float*)d_in[8];
    const float* enc_bih = (const float*)d_in[9];
    const float* enc_bhh = (const float*)d_in[10];
    const float* dec_wih = (const float*)d_in[11];
    const float* dec_whh = (const float*)d_in[12];
    const float* dec_bih = (const float*)d_in[13];
    const float* dec_bhh = (const float*)d_in[14];
    const float* fc1_w   = (const float*)d_in[15];
    const float* fc1_b   = (const float*)d_in[16];
    const float* fc2_w   = (const float*)d_in[17];
    const float* fc2_b   = (const float*)d_in[18];
    const float* fc3_w   = (const float*)d_in[19];
    const float* fc3_b   = (const float*)d_in[20];
    float* out = (float*)d_out;

    float *xsT, *hbase, *hdbase, *m1, *m2;
    cudaGetSymbolAddress((void**)&xsT,    g_xsT);
    cudaGetSymbolAddress((void**)&hbase,  g_h);
    cudaGetSymbolAddress((void**)&hdbase, g_hd);
    cudaGetSymbolAddress((void**)&m1,     g_m1);
    cudaGetSymbolAddress((void**)&m2,     g_m2);

    float* hbuf[2]  = {hbase,  hbase  + (size_t)BB * HH};
    float* hdbuf[2] = {hdbase, hdbase + (size_t)BB * HH};

    // zero initial hidden states (must happen every launch for determinism)
    cudaMemsetAsync(hbuf[0],  0, (size_t)BB * HH * sizeof(float));
    cudaMemsetAsync(hdbuf[0], 0, (size_t)BB * HH * sizeof(float));

    conv_bn_kernel<<<BB * TT, 128>>>(past, conv_w, conv_b, bn_g, bn_b, bn_m, bn_v);
    present_init_kernel<<<(BB * 6 + 255) / 256, 256>>>(past);

    dim3 ggrid(BB / 64, 2);

    // encoder: 128 recurrent steps
    for (int t = 0; t < TT; ++t) {
        const float* Ax = xsT + (size_t)t * BB * HH;
        gru_step_kernel<<<ggrid, 256>>>(Ax, hbuf[t & 1],
                                        enc_wih, enc_whh, enc_bih, enc_bhh,
                                        hbuf[(t + 1) & 1], 1);
    }
    const float* henc = hbuf[TT & 1];  // final encoder state (= hbuf[0])

    // decoder: 30 steps, x nonzero only at step 0
    for (int s = 0; s < NSTEPS; ++s) {
        int hasx = (s == 0) ? 1 : 0;
        gru_step_kernel<<<ggrid, 256>>>(hasx ? henc : nullptr, hdbuf[s & 1],
                                        dec_wih, dec_whh, dec_bih, dec_bhh,
                                        hdbuf[(s + 1) & 1], hasx);
        const float* hcur = hdbuf[(s + 1) & 1];
        gemm_bias_act_kernel<true ><<<dim3(BB / 64, 4), 256>>>(hcur, fc1_w, fc1_b, m1, 128, 256);
        gemm_bias_act_kernel<false><<<dim3(BB / 64, 1), 256>>>(m1,   fc2_w, fc2_b, m2, 256, 64);
        mlp3_kernel<<<(BB * 6 + 255) / 256, 256>>>(fc3_w, fc3_b, out, s);
    }

    (void)in_sizes; (void)n_in; (void)out_size;
}

// round 9
// speedup vs baseline: 1.0033x; 1.0033x over previous
#include <cuda_runtime.h>
#include <math.h>

#define BB 8192
#define TT 128
#define HH 128
#define NSTEPS 30
#define KC 16

// ---------------- scratch (device globals; no allocation allowed) ----------------
__device__ float g_xsT[(size_t)TT * BB * HH];   // conv output, layout [t][b][h]
__device__ float g_h [2][(size_t)BB * HH];      // encoder hidden ping-pong
__device__ float g_hd[2][(size_t)BB * HH];      // decoder hidden ping-pong
__device__ float g_m1[(size_t)BB * 256];        // mlp fc1 out
__device__ float g_m2[(size_t)BB * 64];         // mlp fc2 out
__device__ float g_present[(size_t)BB * 6];     // running present accumulator

__device__ __forceinline__ float sigmoidf_(float x) { return 1.0f / (1.0f + expf(-x)); }

// ---------------- conv1d(k=3,pad=1) + relu + batchnorm -> g_xsT[t][b][h] ----------------
__global__ void conv_bn_kernel(const float* __restrict__ past,
                               const float* __restrict__ cw,
                               const float* __restrict__ cb,
                               const float* __restrict__ bn_g,
                               const float* __restrict__ bn_b,
                               const float* __restrict__ bn_m,
                               const float* __restrict__ bn_v)
{
    int bt = blockIdx.x;
    int b = bt >> 7;          // / 128
    int t = bt & 127;
    int h = threadIdx.x;

    float scale = bn_g[0] * rsqrtf(bn_v[0] + 1e-5f);
    float shift = bn_b[0] - bn_m[0] * scale;

    float pv[6][3];
#pragma unroll
    for (int c = 0; c < 6; ++c)
#pragma unroll
        for (int k = 0; k < 3; ++k) {
            int tt = t + k - 1;
            pv[c][k] = (tt >= 0 && tt < TT) ? past[(size_t)b * 768 + c * 128 + tt] : 0.0f;
        }

    float acc = cb[h];
#pragma unroll
    for (int c = 0; c < 6; ++c)
#pragma unroll
        for (int k = 0; k < 3; ++k)
            acc = fmaf(pv[c][k], cw[h * 18 + c * 3 + k], acc);

    acc = fmaxf(acc, 0.0f);
    acc = acc * scale + shift;
    g_xsT[((size_t)t * BB + b) * HH + h] = acc;
}

// ---------------- present0 = past[:, :, T-1] ----------------
__global__ void present_init_kernel(const float* __restrict__ past)
{
    int i = blockIdx.x * blockDim.x + threadIdx.x;
    if (i >= BB * 6) return;
    int b = i / 6, c = i % 6;
    g_present[i] = past[(size_t)b * 768 + c * 128 + (TT - 1)];
}

// ---------------- fused GRU step: gates GEMM (K = [x|h] concat) + pointwise update --------
// Tile: 64 rows (batch) x 64 cols (hidden) per CTA, 256 threads, 4x4 per thread,
// 4 accumulator sets (r, z, in, hn); only 3 active per K-phase.
__global__ __launch_bounds__(256, 2) void gru_step_kernel(
    const float* __restrict__ Ax,   // [B][128] x-input (may be null when hasx == 0)
    const float* __restrict__ Ah,   // [B][128] h_in
    const float* __restrict__ Wih,  // [384][128]
    const float* __restrict__ Whh,  // [384][128]
    const float* __restrict__ bih,
    const float* __restrict__ bhh,
    float* __restrict__ Hout,       // [B][128]
    int hasx)
{
    __shared__ float As[KC][68];    // [k][row], padded
    __shared__ float Ws[KC][196];   // [k][gate*64 + jj], padded

    const int tid = threadIdx.x;
    const int tx = tid & 15;        // col group
    const int ty = tid >> 4;        // row group
    const int bm = blockIdx.x * 64;
    const int bj = blockIdx.y * 64;

    float aR[16], aZ[16], aIN[16], aHN[16];
#pragma unroll
    for (int i = 0; i < 16; ++i) { aR[i] = 0.f; aZ[i] = 0.f; aIN[i] = 0.f; aHN[i] = 0.f; }

    const int lrow = tid >> 2;          // 0..63
    const int lk0  = (tid & 3) * 4;     // 0,4,8,12

#pragma unroll
    for (int phase = 0; phase < 2; ++phase) {
        if (phase == 0 && !hasx) continue;
        const float* __restrict__ A = phase ? Ah : Ax;
        const float* __restrict__ W = phase ? Whh : Wih;

        for (int kc = 0; kc < 128; kc += KC) {
            __syncthreads();
            {
                float4 v = *reinterpret_cast<const float4*>(&A[(size_t)(bm + lrow) * HH + kc + lk0]);
                As[lk0 + 0][lrow] = v.x; As[lk0 + 1][lrow] = v.y;
                As[lk0 + 2][lrow] = v.z; As[lk0 + 3][lrow] = v.w;
            }
#pragma unroll
            for (int it = 0; it < 3; ++it) {
                int r  = lrow + it * 64;        // 0..191
                int gg = r >> 6, jj = r & 63;
                float4 v = *reinterpret_cast<const float4*>(
                    &W[(size_t)(gg * 128 + bj + jj) * HH + kc + lk0]);
                Ws[lk0 + 0][r] = v.x; Ws[lk0 + 1][r] = v.y;
                Ws[lk0 + 2][r] = v.z; Ws[lk0 + 3][r] = v.w;
            }
            __syncthreads();

#pragma unroll
            for (int k = 0; k < KC; ++k) {
                float4 a4 = *reinterpret_cast<const float4*>(&As[k][ty * 4]);
                float4 w0 = *reinterpret_cast<const float4*>(&Ws[k][tx * 4]);
                float4 w1 = *reinterpret_cast<const float4*>(&Ws[k][64 + tx * 4]);
                float4 w2 = *reinterpret_cast<const float4*>(&Ws[k][128 + tx * 4]);
                float a[4]  = {a4.x, a4.y, a4.z, a4.w};
                float wr[4] = {w0.x, w0.y, w0.z, w0.w};
                float wz[4] = {w1.x, w1.y, w1.z, w1.w};
                float wn[4] = {w2.x, w2.y, w2.z, w2.w};
#pragma unroll
                for (int i = 0; i < 4; ++i)
#pragma unroll
                    for (int j = 0; j < 4; ++j) {
                        aR[i * 4 + j] = fmaf(a[i], wr[j], aR[i * 4 + j]);
                        aZ[i * 4 + j] = fmaf(a[i], wz[j], aZ[i * 4 + j]);
                        if (phase == 0) aIN[i * 4 + j] = fmaf(a[i], wn[j], aIN[i * 4 + j]);
                        else            aHN[i * 4 + j] = fmaf(a[i], wn[j], aHN[i * 4 + j]);
                    }
            }
        }
    }

    // ---- fused GRU pointwise epilogue ----
#pragma unroll
    for (int j = 0; j < 4; ++j) {
        int col = bj + tx * 4 + j;
        float br  = bih[col] + bhh[col];
        float bz  = bih[128 + col] + bhh[128 + col];
        float bin = bih[256 + col];
        float bhn = bhh[256 + col];
#pragma unroll
        for (int i = 0; i < 4; ++i) {
            int row = bm + ty * 4 + i;
            float r = sigmoidf_(aR[i * 4 + j] + br);
            float z = sigmoidf_(aZ[i * 4 + j] + bz);
            float n = tanhf(aIN[i * 4 + j] + bin + r * (aHN[i * 4 + j] + bhn));
            float hp = Ah[(size_t)row * HH + col];
            Hout[(size_t)row * HH + col] = (1.0f - z) * n + z * hp;
        }
    }
}

// ---------------- generic tiled GEMM: C[M][N] = act(A[M][K] @ W[N][K]^T + bias) ----------
template <bool RELU>
__global__ __launch_bounds__(256) void gemm_bias_act_kernel(
    const float* __restrict__ A, const float* __restrict__ W,
    const float* __restrict__ bias, float* __restrict__ C,
    int K, int N)
{
    __shared__ float As[KC][68];
    __shared__ float Ws[KC][68];

    const int tid = threadIdx.x;
    const int tx = tid & 15, ty = tid >> 4;
    const int bm = blockIdx.x * 64;
    const int bn = blockIdx.y * 64;

    float acc[16];
#pragma unroll
    for (int i = 0; i < 16; ++i) acc[i] = 0.f;

    const int lrow = tid >> 2;
    const int lk0  = (tid & 3) * 4;

    for (int kc = 0; kc < K; kc += KC) {
        __syncthreads();
        {
            float4 v = *reinterpret_cast<const float4*>(&A[(size_t)(bm + lrow) * K + kc + lk0]);
            As[lk0 + 0][lrow] = v.x; As[lk0 + 1][lrow] = v.y;
            As[lk0 + 2][lrow] = v.z; As[lk0 + 3][lrow] = v.w;
        }
        {
            float4 v = *reinterpret_cast<const float4*>(&W[(size_t)(bn + lrow) * K + kc + lk0]);
            Ws[lk0 + 0][lrow] = v.x; Ws[lk0 + 1][lrow] = v.y;
            Ws[lk0 + 2][lrow] = v.z; Ws[lk0 + 3][lrow] = v.w;
        }
        __syncthreads();
#pragma unroll
        for (int k = 0; k < KC; ++k) {
            float4 a4 = *reinterpret_cast<const float4*>(&As[k][ty * 4]);
            float4 w4 = *reinterpret_cast<const float4*>(&Ws[k][tx * 4]);
            float a[4] = {a4.x, a4.y, a4.z, a4.w};
            float w[4] = {w4.x, w4.y, w4.z, w4.w};
#pragma unroll
            for (int i = 0; i < 4; ++i)
#pragma unroll
                for (int j = 0; j < 4; ++j)
                    acc[i * 4 + j] = fmaf(a[i], w[j], acc[i * 4 + j]);
        }
    }

#pragma unroll
    for (int j = 0; j < 4; ++j) {
        int col = bn + tx * 4 + j;
        float b = bias[col];
#pragma unroll
        for (int i = 0; i < 4; ++i) {
            float v = acc[i * 4 + j] + b;
            if (RELU) v = fmaxf(v, 0.0f);
            C[(size_t)(bm + ty * 4 + i) * N + col] = v;
        }
    }
}

// ---------------- fc3 + present accumulate + output write ----------------
__global__ void mlp3_kernel(const float* __restrict__ W,   // [6][64]
                            const float* __restrict__ bias,
                            float* __restrict__ out, int s)
{
    int i = blockIdx.x * blockDim.x + threadIdx.x;
    if (i >= BB * 6) return;
    int b = i / 6, c = i % 6;
    float acc = bias[c];
    const float* arow = &g_m2[(size_t)b * 64];
    const float* wrow = &W[c * 64];
#pragma unroll
    for (int k = 0; k < 64; ++k) acc = fmaf(arow[k], wrow[k], acc);
    float p = g_present[i] + acc;
    g_present[i] = p;
    out[(size_t)b * (6 * NSTEPS) + c * NSTEPS + s] = p;
}

// ---------------- launcher ----------------
extern "C" void kernel_launch(void* const* d_in, const int* in_sizes, int n_in,
                              void* d_out, int out_size)
{
    const float* past    = (const float*)d_in[0];
    const float* conv_w  = (const float*)d_in[1];
    const float* conv_b  = (const float*)d_in[2];
    const float* bn_g    = (const float*)d_in[3];
    const float* bn_b    = (const float*)d_in[4];
    const float* bn_m    = (const float*)d_in[5];
    const float* bn_v    = (const float*)d_in[6];
    const float* enc_wih = (const float*)d_in[7];
    const float* enc_whh = (const float*)d_in[8];
    const float* enc_bih = (const float*)d_in[9];
    const float* enc_bhh = (const float*)d_in[10];
    const float* dec_wih = (const float*)d_in[11];
    const float* dec_whh = (const float*)d_in[12];
    const float* dec_bih = (const float*)d_in[13];
    const float* dec_bhh = (const float*)d_in[14];
    const float* fc1_w   = (const float*)d_in[15];
    const float* fc1_b   = (const float*)d_in[16];
    const float* fc2_w   = (const float*)d_in[17];
    const float* fc2_b   = (const float*)d_in[18];
    const float* fc3_w   = (const float*)d_in[19];
    const float* fc3_b   = (const float*)d_in[20];
    float* out = (float*)d_out;

    float *xsT, *hbase, *hdbase, *m1, *m2;
    cudaGetSymbolAddress((void**)&xsT,    g_xsT);
    cudaGetSymbolAddress((void**)&hbase,  g_h);
    cudaGetSymbolAddress((void**)&hdbase, g_hd);
    cudaGetSymbolAddress((void**)&m1,     g_m1);
    cudaGetSymbolAddress((void**)&m2,     g_m2);

    float* hbuf[2]  = {hbase,  hbase  + (size_t)BB * HH};
    float* hdbuf[2] = {hdbase, hdbase + (size_t)BB * HH};

    // zero initial hidden states (must happen every launch for determinism)
    cudaMemsetAsync(hbuf[0],  0, (size_t)BB * HH * sizeof(float));
    cudaMemsetAsync(hdbuf[0], 0, (size_t)BB * HH * sizeof(float));

    conv_bn_kernel<<<BB * TT, 128>>>(past, conv_w, conv_b, bn_g, bn_b, bn_m, bn_v);
    present_init_kernel<<<(BB * 6 + 255) / 256, 256>>>(past);

    dim3 ggrid(BB / 64, 2);

    // encoder: 128 recurrent steps
    for (int t = 0; t < TT; ++t) {
        const float* Ax = xsT + (size_t)t * BB * HH;
        gru_step_kernel<<<ggrid, 256>>>(Ax, hbuf[t & 1],
                                        enc_wih, enc_whh, enc_bih, enc_bhh,
                                        hbuf[(t + 1) & 1], 1);
    }
    const float* henc = hbuf[TT & 1];  // final encoder state (= hbuf[0])

    // decoder: 30 steps, x nonzero only at step 0
    for (int s = 0; s < NSTEPS; ++s) {
        int hasx = (s == 0) ? 1 : 0;
        gru_step_kernel<<<ggrid, 256>>>(hasx ? henc : nullptr, hdbuf[s & 1],
                                        dec_wih, dec_whh, dec_bih, dec_bhh,
                                        hdbuf[(s + 1) & 1], hasx);
        const float* hcur = hdbuf[(s + 1) & 1];
        gemm_bias_act_kernel<true ><<<dim3(BB / 64, 4), 256>>>(hcur, fc1_w, fc1_b, m1, 128, 256);
        gemm_bias_act_kernel<false><<<dim3(BB / 64, 1), 256>>>(m1,   fc2_w, fc2_b, m2, 256, 64);
        mlp3_kernel<<<(BB * 6 + 255) / 256, 256>>>(fc3_w, fc3_b, out, s);
    }

    (void)in_sizes; (void)n_in; (void)out_size;
}